// round 8
// baseline (speedup 1.0000x reference)
#include <cuda_runtime.h>
#include <cuda_bf16.h>
#include <stdint.h>

#define BH 64
#define KP 512
#define NN 4096
#define DD 64
#define XT 16384            // 128 x 64 bf16 tile (z pass)

// ---- hm_main smem layout (bytes): 64x64 tiles ----
#define M_X(b,c)  ((b) * 32768 + (c) * 8192)   // c: 0=xkhi 1=xklo 2=xvhi 3=xvlo
#define M_KHI 65536
#define M_KLO 73728
#define M_WHI 81920
#define M_WLO 90112
#define M_RZ  98304         // 2 x 256B raw z values
#define M_SP  98816         // 4 x 64 floats
#define M_RS  99840         // 64 floats
#define M_SMEM 100352

// ---- hm_z smem layout (128x128 tiles, unchanged from R7) ----
#define Z_XHI 0
#define Z_XLO XT
#define Z_K(b,c) (32768 + (b) * 32768 + (c) * XT)
#define Z_ZP 98304
#define Z_SMEM 99328

__device__ float g_z[BH * NN];
__device__ __align__(16) __nv_bfloat16 g_K_hi[BH * KP * DD];
__device__ __align__(16) __nv_bfloat16 g_K_lo[BH * KP * DD];
__device__ __align__(16) __nv_bfloat16 g_xk_hi[BH * NN * DD];
__device__ __align__(16) __nv_bfloat16 g_xk_lo[BH * NN * DD];
__device__ __align__(16) __nv_bfloat16 g_xv_hi[BH * NN * DD];
__device__ __align__(16) __nv_bfloat16 g_xv_lo[BH * NN * DD];

// ---------------------------------------------------------------- helpers
__device__ __forceinline__ uint32_t s2u(const void* p) {
    return (uint32_t)__cvta_generic_to_shared(p);
}
__device__ __forceinline__ void mma_bf16(float* c, const uint32_t* a, const uint32_t* b) {
    asm volatile(
        "mma.sync.aligned.m16n8k16.row.col.f32.bf16.bf16.f32 "
        "{%0,%1,%2,%3}, {%4,%5,%6,%7}, {%8,%9}, {%0,%1,%2,%3};"
        : "+f"(c[0]), "+f"(c[1]), "+f"(c[2]), "+f"(c[3])
        : "r"(a[0]), "r"(a[1]), "r"(a[2]), "r"(a[3]), "r"(b[0]), "r"(b[1]));
}
__device__ __forceinline__ void ldsm4(uint32_t* r, uint32_t addr) {
    asm volatile("ldmatrix.sync.aligned.m8n8.x4.shared.b16 {%0,%1,%2,%3}, [%4];"
        : "=r"(r[0]), "=r"(r[1]), "=r"(r[2]), "=r"(r[3]) : "r"(addr));
}
__device__ __forceinline__ void ldsm4t(uint32_t* r, uint32_t addr) {
    asm volatile("ldmatrix.sync.aligned.m8n8.x4.trans.shared.b16 {%0,%1,%2,%3}, [%4];"
        : "=r"(r[0]), "=r"(r[1]), "=r"(r[2]), "=r"(r[3]) : "r"(addr));
}
__device__ __forceinline__ void cpa(uint32_t dst, const void* src) {
    asm volatile("cp.async.cg.shared.global [%0], [%1], 16;" :: "r"(dst), "l"(src));
}
#define CPA_COMMIT() asm volatile("cp.async.commit_group;" ::: "memory")
__device__ __forceinline__ void cpa_wait1() { asm volatile("cp.async.wait_group 1;" ::: "memory"); }

// 128x64 bf16 tile (16KB) global -> swizzled smem (128B rows). 256 thr.
__device__ __forceinline__ void cpa_tile(uint32_t sbase, const __nv_bfloat16* g, int tid) {
#pragma unroll
    for (int j = 0; j < 4; j++) {
        int ch = tid + j * 256;
        int row = ch >> 3, c = ch & 7;
        uint32_t off = (uint32_t)row * 128 + (((uint32_t)c * 16) ^ (((uint32_t)row & 7) << 4));
        cpa(sbase + off, (const char*)g + (size_t)ch * 16);
    }
}
// 64x64 bf16 tile (8KB) global -> swizzled smem. 256 thr.
__device__ __forceinline__ void cpa_tile64(uint32_t sbase, const __nv_bfloat16* g, int tid) {
#pragma unroll
    for (int j = 0; j < 2; j++) {
        int ch = tid + j * 256;
        int row = ch >> 3, c = ch & 7;
        uint32_t off = (uint32_t)row * 128 + (((uint32_t)c * 16) ^ (((uint32_t)row & 7) << 4));
        cpa(sbase + off, (const char*)g + (size_t)ch * 16);
    }
}

// GEMM-A (z pass): C[4 mb][4 j][4] += (Khi+Klo)[64k x 64d] @ (xhi+xlo)[32n x 64d]^T
__device__ __forceinline__ void gemmA(float C[4][4][4],
        uint32_t uKhi, uint32_t uKlo, uint32_t uXhi, uint32_t uXlo,
        int kw, int nw, int lane) {
    const uint32_t sx = ((uint32_t)lane & 7) << 4;
    const uint32_t ar = (uint32_t)(kw * 64 + (lane & 15));
    const uint32_t br = (uint32_t)(nw * 32 + ((lane >> 4) & 1) * 8 + (lane & 7));
#pragma unroll
    for (int kc = 0; kc < 4; kc++) {
        const uint32_t acol = ((((uint32_t)lane >> 4) & 1) * 16 + kc * 32) ^ sx;
        const uint32_t bcol = ((((uint32_t)lane >> 3) & 1) * 16 + kc * 32) ^ sx;
        uint32_t ah[4][4], al[4][4], bh2[2][4], bl2[2][4];
#pragma unroll
        for (int mb = 0; mb < 4; mb++) {
            ldsm4(ah[mb], uKhi + (ar + mb * 16) * 128 + acol);
            ldsm4(al[mb], uKlo + (ar + mb * 16) * 128 + acol);
        }
#pragma unroll
        for (int g = 0; g < 2; g++) {
            ldsm4(bh2[g], uXhi + (br + g * 16) * 128 + bcol);
            ldsm4(bl2[g], uXlo + (br + g * 16) * 128 + bcol);
        }
#pragma unroll
        for (int mb = 0; mb < 4; mb++)
#pragma unroll
            for (int g = 0; g < 2; g++)
#pragma unroll
                for (int nbb = 0; nbb < 2; nbb++)
                    mma_bf16(C[mb][g * 2 + nbb], ah[mb], &bh2[g][nbb * 2]);
#pragma unroll
        for (int mb = 0; mb < 4; mb++)
#pragma unroll
            for (int g = 0; g < 2; g++)
#pragma unroll
                for (int nbb = 0; nbb < 2; nbb++)
                    mma_bf16(C[mb][g * 2 + nbb], ah[mb], &bl2[g][nbb * 2]);
#pragma unroll
        for (int mb = 0; mb < 4; mb++)
#pragma unroll
            for (int g = 0; g < 2; g++)
#pragma unroll
                for (int nbb = 0; nbb < 2; nbb++)
                    mma_bf16(C[mb][g * 2 + nbb], al[mb], &bh2[g][nbb * 2]);
    }
}

// ---------------------------------------------------------------- split
__global__ __launch_bounds__(256) void hm_split(const float4* __restrict__ src, int which, int n4) {
    int i = blockIdx.x * 256 + threadIdx.x;
    if (i >= n4) return;
    __nv_bfloat16 *hi, *lo;
    if (which == 0)      { hi = g_K_hi;  lo = g_K_lo;  }
    else if (which == 1) { hi = g_xk_hi; lo = g_xk_lo; }
    else                 { hi = g_xv_hi; lo = g_xv_lo; }
    float4 v = src[i];
    __nv_bfloat162 h0 = __floats2bfloat162_rn(v.x, v.y);
    __nv_bfloat162 h1 = __floats2bfloat162_rn(v.z, v.w);
    float2 f0 = __bfloat1622float2(h0), f1 = __bfloat1622float2(h1);
    __nv_bfloat162 l0 = __floats2bfloat162_rn(v.x - f0.x, v.y - f0.y);
    __nv_bfloat162 l1 = __floats2bfloat162_rn(v.z - f1.x, v.w - f1.y);
    uint2 hw, lw;
    hw.x = *(uint32_t*)&h0; hw.y = *(uint32_t*)&h1;
    lw.x = *(uint32_t*)&l0; lw.y = *(uint32_t*)&l1;
    ((uint2*)hi)[i] = hw;
    ((uint2*)lo)[i] = lw;
}

// ---------------------------------------------------------------- pass 1: z (unchanged)
__global__ __launch_bounds__(256) void hm_z() {
    extern __shared__ char sm[];
    const int tid = threadIdx.x, lane = tid & 31, wid = tid >> 5;
    const int kw = wid >> 2, nw = wid & 3;
    const int n0 = blockIdx.x * 128, bh = blockIdx.y;
    uint32_t sb = s2u(sm);

    cpa_tile(sb + Z_XHI, g_xk_hi + ((size_t)bh * NN + n0) * DD, tid);
    cpa_tile(sb + Z_XLO, g_xk_lo + ((size_t)bh * NN + n0) * DD, tid);
    cpa_tile(sb + Z_K(0, 0), g_K_hi + (size_t)bh * KP * DD, tid);
    cpa_tile(sb + Z_K(0, 1), g_K_lo + (size_t)bh * KP * DD, tid);
    CPA_COMMIT();

    float zl[8];
#pragma unroll
    for (int i = 0; i < 8; i++) zl[i] = 0.f;

    for (int kt = 0; kt < 4; kt++) {
        if (kt + 1 < 4) {
            cpa_tile(sb + Z_K((kt + 1) & 1, 0), g_K_hi + ((size_t)bh * KP + (kt + 1) * 128) * DD, tid);
            cpa_tile(sb + Z_K((kt + 1) & 1, 1), g_K_lo + ((size_t)bh * KP + (kt + 1) * 128) * DD, tid);
        }
        CPA_COMMIT();
        cpa_wait1();
        __syncthreads();

        float C[4][4][4];
#pragma unroll
        for (int a = 0; a < 4; a++)
#pragma unroll
            for (int b = 0; b < 4; b++)
#pragma unroll
                for (int c = 0; c < 4; c++) C[a][b][c] = 0.f;
        gemmA(C, sb + Z_K(kt & 1, 0), sb + Z_K(kt & 1, 1), sb + Z_XHI, sb + Z_XLO, kw, nw, lane);
#pragma unroll
        for (int mb = 0; mb < 4; mb++)
#pragma unroll
            for (int j = 0; j < 4; j++) {
                zl[2 * j]     += __expf(C[mb][j][0]) + __expf(C[mb][j][2]);
                zl[2 * j + 1] += __expf(C[mb][j][1]) + __expf(C[mb][j][3]);
            }
        __syncthreads();
    }
#pragma unroll
    for (int i = 0; i < 8; i++) {
        zl[i] += __shfl_xor_sync(~0u, zl[i], 4);
        zl[i] += __shfl_xor_sync(~0u, zl[i], 8);
        zl[i] += __shfl_xor_sync(~0u, zl[i], 16);
    }
    float* zp = (float*)(sm + Z_ZP);
    if (lane < 4) {
#pragma unroll
        for (int j = 0; j < 4; j++)
            *(float2*)&zp[kw * 128 + nw * 32 + j * 8 + lane * 2] =
                make_float2(zl[2 * j], zl[2 * j + 1]);
    }
    __syncthreads();
    if (tid < 128)
        g_z[(size_t)bh * NN + n0 + tid] = zp[tid] + zp[128 + tid];
}

// ---------------------------------------------------------------- pass 2: 64k x 64n CTA, 2 CTAs/SM
__global__ __launch_bounds__(256, 2) void hm_main(const float* __restrict__ K,
        const float* __restrict__ V, float* __restrict__ out) {
    extern __shared__ char sm[];
    const int tid = threadIdx.x, lane = tid & 31, wid = tid >> 5;
    const int kw = wid >> 2, nw = wid & 3;
    const int k0 = blockIdx.x * 64, bh = blockIdx.y;
    uint32_t sb = s2u(sm);
    const uint32_t sx = ((uint32_t)lane & 7) << 4;

    // prologue: K tiles + x(0) + z(0)
    cpa_tile64(sb + M_KHI, g_K_hi + ((size_t)bh * KP + k0) * DD, tid);
    cpa_tile64(sb + M_KLO, g_K_lo + ((size_t)bh * KP + k0) * DD, tid);
    cpa_tile64(sb + M_X(0, 0), g_xk_hi + (size_t)bh * NN * DD, tid);
    cpa_tile64(sb + M_X(0, 1), g_xk_lo + (size_t)bh * NN * DD, tid);
    cpa_tile64(sb + M_X(0, 2), g_xv_hi + (size_t)bh * NN * DD, tid);
    cpa_tile64(sb + M_X(0, 3), g_xv_lo + (size_t)bh * NN * DD, tid);
    if (tid < 16) cpa(sb + M_RZ + tid * 16, g_z + (size_t)bh * NN + tid * 4);
    CPA_COMMIT();

    float accK[2][2][4], accV[2][2][4], sloc[4];
#pragma unroll
    for (int a = 0; a < 2; a++)
#pragma unroll
        for (int b = 0; b < 2; b++)
#pragma unroll
            for (int c = 0; c < 4; c++) { accK[a][b][c] = 0.f; accV[a][b][c] = 0.f; }
#pragma unroll
    for (int i = 0; i < 4; i++) sloc[i] = 0.f;

    // GEMM-A addressing
    const uint32_t ar = (uint32_t)(kw * 32 + (lane & 15));
    const uint32_t br = (uint32_t)(nw * 16 + ((lane >> 4) & 1) * 8 + (lane & 7));
    // GEMM-B addressing
    const uint32_t wr = ar;
    const uint32_t xr = (uint32_t)(((lane >> 3) & 1) * 8 + (lane & 7));
    const uint32_t xcol = ((uint32_t)(nw * 32 + ((lane >> 4) & 1) * 16)) ^ sx;
    const uint32_t wsx = (((uint32_t)(lane >> 2) & 7)) << 4;

    for (int it = 0; it < NN / 64; it++) {
        const int b = it & 1;
        if (it + 1 < NN / 64) {
            const size_t n1 = (size_t)bh * NN + (size_t)(it + 1) * 64;
            cpa_tile64(sb + M_X(b ^ 1, 0), g_xk_hi + n1 * DD, tid);
            cpa_tile64(sb + M_X(b ^ 1, 1), g_xk_lo + n1 * DD, tid);
            cpa_tile64(sb + M_X(b ^ 1, 2), g_xv_hi + n1 * DD, tid);
            cpa_tile64(sb + M_X(b ^ 1, 3), g_xv_lo + n1 * DD, tid);
            if (tid < 16) cpa(sb + M_RZ + (b ^ 1) * 256 + tid * 16, g_z + n1 + tid * 4);
        }
        CPA_COMMIT();
        cpa_wait1();
        __syncthreads();

        // ---- GEMM-A: dists[64k,64n], 3-term split, term-major order ----
        float C[2][2][4];
#pragma unroll
        for (int a = 0; a < 2; a++)
#pragma unroll
            for (int bb = 0; bb < 2; bb++)
#pragma unroll
                for (int c = 0; c < 4; c++) C[a][bb][c] = 0.f;
        {
            const uint32_t uKhi = sb + M_KHI, uKlo = sb + M_KLO;
            const uint32_t uXhi = sb + M_X(b, 0), uXlo = sb + M_X(b, 1);
#pragma unroll
            for (int kc = 0; kc < 4; kc++) {
                const uint32_t acol = ((((uint32_t)lane >> 4) & 1) * 16 + kc * 32) ^ sx;
                const uint32_t bcol = ((((uint32_t)lane >> 3) & 1) * 16 + kc * 32) ^ sx;
                uint32_t ah[2][4], al[2][4], bh2[4], bl2[4];
#pragma unroll
                for (int mb = 0; mb < 2; mb++) {
                    ldsm4(ah[mb], uKhi + (ar + mb * 16) * 128 + acol);
                    ldsm4(al[mb], uKlo + (ar + mb * 16) * 128 + acol);
                }
                ldsm4(bh2, uXhi + br * 128 + bcol);
                ldsm4(bl2, uXlo + br * 128 + bcol);
#pragma unroll
                for (int mb = 0; mb < 2; mb++)
#pragma unroll
                    for (int nbb = 0; nbb < 2; nbb++)
                        mma_bf16(C[mb][nbb], ah[mb], &bh2[nbb * 2]);
#pragma unroll
                for (int mb = 0; mb < 2; mb++)
#pragma unroll
                    for (int nbb = 0; nbb < 2; nbb++)
                        mma_bf16(C[mb][nbb], ah[mb], &bl2[nbb * 2]);
#pragma unroll
                for (int mb = 0; mb < 2; mb++)
#pragma unroll
                    for (int nbb = 0; nbb < 2; nbb++)
                        mma_bf16(C[mb][nbb], al[mb], &bh2[nbb * 2]);
            }
        }

        // ---- epilogue: w = exp(d)/z -> split -> swizzled W smem; S partials ----
        {
            const float* zbuf = (const float*)(sm + M_RZ + b * 256);
#pragma unroll
            for (int j = 0; j < 2; j++) {
                int n = nw * 16 + j * 8 + (lane & 3) * 2;
                float rz0 = __fdividef(1.0f, zbuf[n]);
                float rz1 = __fdividef(1.0f, zbuf[n + 1]);
#pragma unroll
                for (int mb = 0; mb < 2; mb++)
#pragma unroll
                    for (int rg = 0; rg < 2; rg++) {
                        int k = kw * 32 + mb * 16 + rg * 8 + (lane >> 2);
                        float w0 = __expf(C[mb][j][rg * 2])     * rz0;
                        float w1 = __expf(C[mb][j][rg * 2 + 1]) * rz1;
                        sloc[mb * 2 + rg] += w0 + w1;
                        __nv_bfloat162 hp = __floats2bfloat162_rn(w0, w1);
                        float2 hf = __bfloat1622float2(hp);
                        __nv_bfloat162 lp = __floats2bfloat162_rn(w0 - hf.x, w1 - hf.y);
                        uint32_t co = ((uint32_t)(n * 2)) ^ wsx;
                        *(uint32_t*)(sm + M_WHI + (uint32_t)k * 128 + co) = *(uint32_t*)&hp;
                        *(uint32_t*)(sm + M_WLO + (uint32_t)k * 128 + co) = *(uint32_t*)&lp;
                    }
            }
        }
        __syncthreads();

        // ---- GEMM-B: accK += w @ xk, accV += w @ xv (contraction n=64) ----
#pragma unroll
        for (int ks = 0; ks < 4; ks++) {
            const uint32_t wcol = ((((uint32_t)lane >> 4) & 1) * 16 + (uint32_t)ks * 32) ^ sx;
            uint32_t awh[2][4], awl[2][4];
#pragma unroll
            for (int mb = 0; mb < 2; mb++) {
                ldsm4(awh[mb], sb + M_WHI + (wr + mb * 16) * 128 + wcol);
                ldsm4(awl[mb], sb + M_WLO + (wr + mb * 16) * 128 + wcol);
            }
            uint32_t bkh[4], bkl[4], bvh[4], bvl[4];
            ldsm4t(bkh, sb + M_X(b, 0) + (xr + ks * 16) * 128 + xcol);
            ldsm4t(bkl, sb + M_X(b, 1) + (xr + ks * 16) * 128 + xcol);
            ldsm4t(bvh, sb + M_X(b, 2) + (xr + ks * 16) * 128 + xcol);
            ldsm4t(bvl, sb + M_X(b, 3) + (xr + ks * 16) * 128 + xcol);
#pragma unroll
            for (int mb = 0; mb < 2; mb++)
#pragma unroll
                for (int g = 0; g < 2; g++) {
                    mma_bf16(accK[mb][g], awh[mb], &bkh[g * 2]);
                    mma_bf16(accV[mb][g], awh[mb], &bvh[g * 2]);
                    mma_bf16(accK[mb][g], awh[mb], &bkl[g * 2]);
                    mma_bf16(accV[mb][g], awh[mb], &bvl[g * 2]);
                    mma_bf16(accK[mb][g], awl[mb], &bkh[g * 2]);
                    mma_bf16(accV[mb][g], awl[mb], &bvh[g * 2]);
                }
        }
        __syncthreads();
    }

    // ---- S reduction: quad shfl + across 4 nw warps via smem ----
#pragma unroll
    for (int i = 0; i < 4; i++) {
        sloc[i] += __shfl_xor_sync(~0u, sloc[i], 1);
        sloc[i] += __shfl_xor_sync(~0u, sloc[i], 2);
    }
    float* sp = (float*)(sm + M_SP);
    float* rs = (float*)(sm + M_RS);
    if ((lane & 3) == 0) {
#pragma unroll
        for (int mb = 0; mb < 2; mb++)
#pragma unroll
            for (int rg = 0; rg < 2; rg++) {
                int k = kw * 32 + mb * 16 + rg * 8 + (lane >> 2);
                sp[nw * 64 + k] = sloc[mb * 2 + rg];
            }
    }
    __syncthreads();
    if (tid < 64)
        rs[tid] = 1.0f / (sp[tid] + sp[64 + tid] + sp[128 + tid] + sp[192 + tid]);
    __syncthreads();

    // ---- finalize: gK = accK*rs - K, gV = accV*rs - V ----
#pragma unroll
    for (int mb = 0; mb < 2; mb++)
#pragma unroll
        for (int g = 0; g < 2; g++)
#pragma unroll
            for (int rg = 0; rg < 2; rg++) {
                int k = kw * 32 + mb * 16 + rg * 8 + (lane >> 2);
                int d = nw * 16 + g * 8 + (lane & 3) * 2;
                float r = rs[k];
                size_t gi = ((size_t)bh * KP + k0 + k) * DD + d;
                float2 kv = *(const float2*)(K + gi);
                float2 vv = *(const float2*)(V + gi);
                float2 ok, ov;
                ok.x = accK[mb][g][rg * 2]     * r - kv.x;
                ok.y = accK[mb][g][rg * 2 + 1] * r - kv.y;
                ov.x = accV[mb][g][rg * 2]     * r - vv.x;
                ov.y = accV[mb][g][rg * 2 + 1] * r - vv.y;
                *(float2*)(out + gi) = ok;
                *(float2*)(out + (size_t)BH * KP * DD + gi) = ov;
            }
}

// ---------------------------------------------------------------- launch
extern "C" void kernel_launch(void* const* d_in, const int* in_sizes, int n_in,
                              void* d_out, int out_size) {
    (void)in_sizes; (void)n_in; (void)out_size;
    const float* K  = (const float*)d_in[0];
    const float* V  = (const float*)d_in[1];
    const float* xk = (const float*)d_in[2];
    const float* xv = (const float*)d_in[3];
    float* out = (float*)d_out;

    cudaFuncSetAttribute(hm_z,    cudaFuncAttributeMaxDynamicSharedMemorySize, Z_SMEM);
    cudaFuncSetAttribute(hm_main, cudaFuncAttributeMaxDynamicSharedMemorySize, M_SMEM);

    hm_split<<<(BH * KP * DD / 4 + 255) / 256, 256>>>((const float4*)K,  0, BH * KP * DD / 4);
    hm_split<<<(BH * NN * DD / 4 + 255) / 256, 256>>>((const float4*)xk, 1, BH * NN * DD / 4);
    hm_split<<<(BH * NN * DD / 4 + 255) / 256, 256>>>((const float4*)xv, 2, BH * NN * DD / 4);
    hm_z<<<dim3(NN / 128, BH), 256, Z_SMEM>>>();
    hm_main<<<dim3(KP / 64, BH), 256, M_SMEM>>>(K, V, out);
}

// round 9
// speedup vs baseline: 1.0771x; 1.0771x over previous
#include <cuda_runtime.h>
#include <cuda_bf16.h>
#include <stdint.h>

#define BH 64
#define KP 512
#define NN 4096
#define DD 64
#define XT 16384            // 128 x 64 bf16 tile, swizzled, 128B rows

// ---- hm_main smem layout (bytes) ----
#define M_X(b,c)  ((b) * 65536 + (c) * XT)   // c: 0=xkhi 1=xklo 2=xvhi 3=xvlo
#define M_RZ  131072        // 2 x 512B raw z tiles
#define M_SMEM 132096

// ---- hm_z smem layout (unchanged, proven) ----
#define Z_XHI 0
#define Z_XLO XT
#define Z_K(b,c) (32768 + (b) * 32768 + (c) * XT)
#define Z_ZP 98304
#define Z_SMEM 99328

__device__ float g_z[BH * NN];
__device__ __align__(16) __nv_bfloat16 g_K_hi[BH * KP * DD];
__device__ __align__(16) __nv_bfloat16 g_K_lo[BH * KP * DD];
__device__ __align__(16) __nv_bfloat16 g_xk_hi[BH * NN * DD];
__device__ __align__(16) __nv_bfloat16 g_xk_lo[BH * NN * DD];
__device__ __align__(16) __nv_bfloat16 g_xv_hi[BH * NN * DD];
__device__ __align__(16) __nv_bfloat16 g_xv_lo[BH * NN * DD];

// ---------------------------------------------------------------- helpers
__device__ __forceinline__ uint32_t s2u(const void* p) {
    return (uint32_t)__cvta_generic_to_shared(p);
}
__device__ __forceinline__ void mma_bf16(float* c, const uint32_t* a, const uint32_t* b) {
    asm volatile(
        "mma.sync.aligned.m16n8k16.row.col.f32.bf16.bf16.f32 "
        "{%0,%1,%2,%3}, {%4,%5,%6,%7}, {%8,%9}, {%0,%1,%2,%3};"
        : "+f"(c[0]), "+f"(c[1]), "+f"(c[2]), "+f"(c[3])
        : "r"(a[0]), "r"(a[1]), "r"(a[2]), "r"(a[3]), "r"(b[0]), "r"(b[1]));
}
__device__ __forceinline__ void ldsm4(uint32_t* r, uint32_t addr) {
    asm volatile("ldmatrix.sync.aligned.m8n8.x4.shared.b16 {%0,%1,%2,%3}, [%4];"
        : "=r"(r[0]), "=r"(r[1]), "=r"(r[2]), "=r"(r[3]) : "r"(addr));
}
__device__ __forceinline__ void ldsm4t(uint32_t* r, uint32_t addr) {
    asm volatile("ldmatrix.sync.aligned.m8n8.x4.trans.shared.b16 {%0,%1,%2,%3}, [%4];"
        : "=r"(r[0]), "=r"(r[1]), "=r"(r[2]), "=r"(r[3]) : "r"(addr));
}
__device__ __forceinline__ void cpa(uint32_t dst, const void* src) {
    asm volatile("cp.async.cg.shared.global [%0], [%1], 16;" :: "r"(dst), "l"(src));
}
#define CPA_COMMIT() asm volatile("cp.async.commit_group;" ::: "memory")
__device__ __forceinline__ void cpa_wait1() { asm volatile("cp.async.wait_group 1;" ::: "memory"); }

// 128x64 bf16 tile (16KB) global -> swizzled smem (128B rows). 256 thr.
__device__ __forceinline__ void cpa_tile(uint32_t sbase, const __nv_bfloat16* g, int tid) {
#pragma unroll
    for (int j = 0; j < 4; j++) {
        int ch = tid + j * 256;
        int row = ch >> 3, c = ch & 7;
        uint32_t off = (uint32_t)row * 128 + (((uint32_t)c * 16) ^ (((uint32_t)row & 7) << 4));
        cpa(sbase + off, (const char*)g + (size_t)ch * 16);
    }
}

// GEMM-A (z pass layout): C[4 mb][4 j][4] += (Khi+Klo)[64k x 64d] @ (xhi+xlo)[32n x 64d]^T
__device__ __forceinline__ void gemmA(float C[4][4][4],
        uint32_t uKhi, uint32_t uKlo, uint32_t uXhi, uint32_t uXlo,
        int kw, int nw, int lane) {
    const uint32_t sx = ((uint32_t)lane & 7) << 4;
    const uint32_t ar = (uint32_t)(kw * 64 + (lane & 15));
    const uint32_t br = (uint32_t)(nw * 32 + ((lane >> 4) & 1) * 8 + (lane & 7));
#pragma unroll
    for (int kc = 0; kc < 4; kc++) {
        const uint32_t acol = ((((uint32_t)lane >> 4) & 1) * 16 + kc * 32) ^ sx;
        const uint32_t bcol = ((((uint32_t)lane >> 3) & 1) * 16 + kc * 32) ^ sx;
        uint32_t ah[4][4], al[4][4], bh2[2][4], bl2[2][4];
#pragma unroll
        for (int mb = 0; mb < 4; mb++) {
            ldsm4(ah[mb], uKhi + (ar + mb * 16) * 128 + acol);
            ldsm4(al[mb], uKlo + (ar + mb * 16) * 128 + acol);
        }
#pragma unroll
        for (int g = 0; g < 2; g++) {
            ldsm4(bh2[g], uXhi + (br + g * 16) * 128 + bcol);
            ldsm4(bl2[g], uXlo + (br + g * 16) * 128 + bcol);
        }
#pragma unroll
        for (int mb = 0; mb < 4; mb++)
#pragma unroll
            for (int g = 0; g < 2; g++)
#pragma unroll
                for (int nbb = 0; nbb < 2; nbb++)
                    mma_bf16(C[mb][g * 2 + nbb], ah[mb], &bh2[g][nbb * 2]);
#pragma unroll
        for (int mb = 0; mb < 4; mb++)
#pragma unroll
            for (int g = 0; g < 2; g++)
#pragma unroll
                for (int nbb = 0; nbb < 2; nbb++)
                    mma_bf16(C[mb][g * 2 + nbb], ah[mb], &bl2[g][nbb * 2]);
#pragma unroll
        for (int mb = 0; mb < 4; mb++)
#pragma unroll
            for (int g = 0; g < 2; g++)
#pragma unroll
                for (int nbb = 0; nbb < 2; nbb++)
                    mma_bf16(C[mb][g * 2 + nbb], al[mb], &bh2[g][nbb * 2]);
    }
}

// ---------------------------------------------------------------- split (all 3 arrays, one launch)
__global__ __launch_bounds__(256) void hm_split(const float4* __restrict__ Ksrc,
        const float4* __restrict__ xksrc, const float4* __restrict__ xvsrc) {
    int which = blockIdx.y;
    int n4 = (which == 0) ? (BH * KP * DD / 4) : (BH * NN * DD / 4);
    int i = blockIdx.x * 256 + threadIdx.x;
    if (i >= n4) return;
    const float4* src = (which == 0) ? Ksrc : (which == 1) ? xksrc : xvsrc;
    __nv_bfloat16* hi = (which == 0) ? g_K_hi : (which == 1) ? g_xk_hi : g_xv_hi;
    __nv_bfloat16* lo = (which == 0) ? g_K_lo : (which == 1) ? g_xk_lo : g_xv_lo;
    float4 v = src[i];
    __nv_bfloat162 h0 = __floats2bfloat162_rn(v.x, v.y);
    __nv_bfloat162 h1 = __floats2bfloat162_rn(v.z, v.w);
    float2 f0 = __bfloat1622float2(h0), f1 = __bfloat1622float2(h1);
    __nv_bfloat162 l0 = __floats2bfloat162_rn(v.x - f0.x, v.y - f0.y);
    __nv_bfloat162 l1 = __floats2bfloat162_rn(v.z - f1.x, v.w - f1.y);
    uint2 hw, lw;
    hw.x = *(uint32_t*)&h0; hw.y = *(uint32_t*)&h1;
    lw.x = *(uint32_t*)&l0; lw.y = *(uint32_t*)&l1;
    ((uint2*)hi)[i] = hw;
    ((uint2*)lo)[i] = lw;
}

// ---------------------------------------------------------------- pass 1: z (unchanged from R7)
__global__ __launch_bounds__(256) void hm_z() {
    extern __shared__ char sm[];
    const int tid = threadIdx.x, lane = tid & 31, wid = tid >> 5;
    const int kw = wid >> 2, nw = wid & 3;
    const int n0 = blockIdx.x * 128, bh = blockIdx.y;
    uint32_t sb = s2u(sm);

    cpa_tile(sb + Z_XHI, g_xk_hi + ((size_t)bh * NN + n0) * DD, tid);
    cpa_tile(sb + Z_XLO, g_xk_lo + ((size_t)bh * NN + n0) * DD, tid);
    cpa_tile(sb + Z_K(0, 0), g_K_hi + (size_t)bh * KP * DD, tid);
    cpa_tile(sb + Z_K(0, 1), g_K_lo + (size_t)bh * KP * DD, tid);
    CPA_COMMIT();

    float zl[8];
#pragma unroll
    for (int i = 0; i < 8; i++) zl[i] = 0.f;

    for (int kt = 0; kt < 4; kt++) {
        if (kt + 1 < 4) {
            cpa_tile(sb + Z_K((kt + 1) & 1, 0), g_K_hi + ((size_t)bh * KP + (kt + 1) * 128) * DD, tid);
            cpa_tile(sb + Z_K((kt + 1) & 1, 1), g_K_lo + ((size_t)bh * KP + (kt + 1) * 128) * DD, tid);
        }
        CPA_COMMIT();
        cpa_wait1();
        __syncthreads();

        float C[4][4][4];
#pragma unroll
        for (int a = 0; a < 4; a++)
#pragma unroll
            for (int b = 0; b < 4; b++)
#pragma unroll
                for (int c = 0; c < 4; c++) C[a][b][c] = 0.f;
        gemmA(C, sb + Z_K(kt & 1, 0), sb + Z_K(kt & 1, 1), sb + Z_XHI, sb + Z_XLO, kw, nw, lane);
#pragma unroll
        for (int mb = 0; mb < 4; mb++)
#pragma unroll
            for (int j = 0; j < 4; j++) {
                zl[2 * j]     += __expf(C[mb][j][0]) + __expf(C[mb][j][2]);
                zl[2 * j + 1] += __expf(C[mb][j][1]) + __expf(C[mb][j][3]);
            }
        __syncthreads();
    }
#pragma unroll
    for (int i = 0; i < 8; i++) {
        zl[i] += __shfl_xor_sync(~0u, zl[i], 4);
        zl[i] += __shfl_xor_sync(~0u, zl[i], 8);
        zl[i] += __shfl_xor_sync(~0u, zl[i], 16);
    }
    float* zp = (float*)(sm + Z_ZP);
    if (lane < 4) {
#pragma unroll
        for (int j = 0; j < 4; j++)
            *(float2*)&zp[kw * 128 + nw * 32 + j * 8 + lane * 2] =
                make_float2(zl[2 * j], zl[2 * j + 1]);
    }
    __syncthreads();
    if (tid < 128)
        g_z[(size_t)bh * NN + n0 + tid] = zp[tid] + zp[128 + tid];
}

// ---------------------------------------------------------------- pass 2
// CTA = (bh, 128-k tile). Warp owns 16 k-rows x ALL 128 n-cols in GEMM-A;
// w stays in registers (C-frag == A-frag identity), GEMM-B consumes directly.
__global__ __launch_bounds__(256) void hm_main(const float* __restrict__ K,
        const float* __restrict__ V, float* __restrict__ out) {
    extern __shared__ char sm[];
    const int tid = threadIdx.x, lane = tid & 31, wid = tid >> 5;
    const int k0 = blockIdx.x * 128, bh = blockIdx.y;
    uint32_t sb = s2u(sm);
    const uint32_t sx = ((uint32_t)lane & 7) << 4;
    const int q = lane & 3, r = lane >> 2;

    // K tiles (static for the CTA) live in registers as A-fragments? No — keep in
    // smem? K is reloaded per kc each iter from the same 2 tiles; put K hi/lo in
    // smem once at the x-region tail is not possible (buffers full). Instead hold
    // K A-fragments in registers: per warp 4 kc x 2(hi/lo) x 4 = 32 regs. Load once.
    uint32_t kfh[4][4], kfl[4][4];

    // prologue: stage K tile via x-buffer 0 slot 0/1, load frags, then reuse buffer.
    cpa_tile(sb + M_X(0, 0), g_K_hi + ((size_t)bh * KP + k0) * DD, tid);
    cpa_tile(sb + M_X(0, 1), g_K_lo + ((size_t)bh * KP + k0) * DD, tid);
    CPA_COMMIT();
    asm volatile("cp.async.wait_group 0;" ::: "memory");
    __syncthreads();
    {
        const uint32_t ar = (uint32_t)(wid * 16 + (lane & 15));
#pragma unroll
        for (int kc = 0; kc < 4; kc++) {
            const uint32_t acol = ((((uint32_t)lane >> 4) & 1) * 16 + kc * 32) ^ sx;
            ldsm4(kfh[kc], sb + M_X(0, 0) + ar * 128 + acol);
            ldsm4(kfl[kc], sb + M_X(0, 1) + ar * 128 + acol);
        }
    }
    __syncthreads();

    // x(0) + z(0)
    cpa_tile(sb + M_X(0, 0), g_xk_hi + (size_t)bh * NN * DD, tid);
    cpa_tile(sb + M_X(0, 1), g_xk_lo + (size_t)bh * NN * DD, tid);
    cpa_tile(sb + M_X(0, 2), g_xv_hi + (size_t)bh * NN * DD, tid);
    cpa_tile(sb + M_X(0, 3), g_xv_lo + (size_t)bh * NN * DD, tid);
    if (tid < 32) cpa(sb + M_RZ + tid * 16, g_z + (size_t)bh * NN + tid * 4);
    CPA_COMMIT();

    float accK[8][4], accV[8][4];
#pragma unroll
    for (int a = 0; a < 8; a++)
#pragma unroll
        for (int c = 0; c < 4; c++) { accK[a][c] = 0.f; accV[a][c] = 0.f; }
    float sloc0 = 0.f, sloc1 = 0.f;

    for (int it = 0; it < NN / 128; it++) {
        const int b = it & 1;
        if (it + 1 < NN / 128) {
            const size_t n1 = (size_t)bh * NN + (size_t)(it + 1) * 128;
            cpa_tile(sb + M_X(b ^ 1, 0), g_xk_hi + n1 * DD, tid);
            cpa_tile(sb + M_X(b ^ 1, 1), g_xk_lo + n1 * DD, tid);
            cpa_tile(sb + M_X(b ^ 1, 2), g_xv_hi + n1 * DD, tid);
            cpa_tile(sb + M_X(b ^ 1, 3), g_xv_lo + n1 * DD, tid);
            if (tid < 32) cpa(sb + M_RZ + (b ^ 1) * 512 + tid * 16, g_z + n1 + tid * 4);
        }
        CPA_COMMIT();
        cpa_wait1();
        __syncthreads();

        // ---- GEMM-A: C[16 j][4] = K[16k x 64d] @ x[128n x 64d]^T, 3-term ----
        float C[16][4];
#pragma unroll
        for (int j = 0; j < 16; j++)
#pragma unroll
            for (int c = 0; c < 4; c++) C[j][c] = 0.f;
        {
            const uint32_t uXhi = sb + M_X(b, 0), uXlo = sb + M_X(b, 1);
            const uint32_t br = (uint32_t)(((lane >> 4) & 1) * 8 + (lane & 7));
#pragma unroll
            for (int kc = 0; kc < 4; kc++) {
                const uint32_t bcol = ((((uint32_t)lane >> 3) & 1) * 16 + kc * 32) ^ sx;
                uint32_t bh2[8][4], bl2[8][4];
#pragma unroll
                for (int jj = 0; jj < 8; jj++) {
                    ldsm4(bh2[jj], uXhi + (br + jj * 16) * 128 + bcol);
                    ldsm4(bl2[jj], uXlo + (br + jj * 16) * 128 + bcol);
                }
#pragma unroll
                for (int jj = 0; jj < 8; jj++) {
                    mma_bf16(C[2 * jj],     kfh[kc], &bh2[jj][0]);
                    mma_bf16(C[2 * jj + 1], kfh[kc], &bh2[jj][2]);
                }
#pragma unroll
                for (int jj = 0; jj < 8; jj++) {
                    mma_bf16(C[2 * jj],     kfh[kc], &bl2[jj][0]);
                    mma_bf16(C[2 * jj + 1], kfh[kc], &bl2[jj][2]);
                }
#pragma unroll
                for (int jj = 0; jj < 8; jj++) {
                    mma_bf16(C[2 * jj],     kfl[kc], &bh2[jj][0]);
                    mma_bf16(C[2 * jj + 1], kfl[kc], &bh2[jj][2]);
                }
            }
        }

        // ---- epilogue in registers: w = exp(C)/z -> bf16 hi/lo A-fragments ----
        uint32_t wh[8][4], wl[8][4];
        {
            const float* zb = (const float*)(sm + M_RZ + b * 512);
#pragma unroll
            for (int nc = 0; nc < 8; nc++) {
                float2 z0 = *(const float2*)&zb[nc * 16 + 2 * q];
                float2 z1 = *(const float2*)&zb[nc * 16 + 8 + 2 * q];
                float r0 = __fdividef(1.f, z0.x), r1 = __fdividef(1.f, z0.y);
                float r2 = __fdividef(1.f, z1.x), r3 = __fdividef(1.f, z1.y);
                float w00 = __expf(C[2 * nc][0]) * r0,  w01 = __expf(C[2 * nc][1]) * r1;
                float w02 = __expf(C[2 * nc][2]) * r0,  w03 = __expf(C[2 * nc][3]) * r1;
                float w10 = __expf(C[2 * nc + 1][0]) * r2, w11 = __expf(C[2 * nc + 1][1]) * r3;
                float w12 = __expf(C[2 * nc + 1][2]) * r2, w13 = __expf(C[2 * nc + 1][3]) * r3;
                sloc0 += (w00 + w01) + (w10 + w11);
                sloc1 += (w02 + w03) + (w12 + w13);
                __nv_bfloat162 h;
                float2 f;
                h = __floats2bfloat162_rn(w00, w01); f = __bfloat1622float2(h);
                wh[nc][0] = *(uint32_t*)&h;
                { __nv_bfloat162 l = __floats2bfloat162_rn(w00 - f.x, w01 - f.y); wl[nc][0] = *(uint32_t*)&l; }
                h = __floats2bfloat162_rn(w02, w03); f = __bfloat1622float2(h);
                wh[nc][1] = *(uint32_t*)&h;
                { __nv_bfloat162 l = __floats2bfloat162_rn(w02 - f.x, w03 - f.y); wl[nc][1] = *(uint32_t*)&l; }
                h = __floats2bfloat162_rn(w10, w11); f = __bfloat1622float2(h);
                wh[nc][2] = *(uint32_t*)&h;
                { __nv_bfloat162 l = __floats2bfloat162_rn(w10 - f.x, w11 - f.y); wl[nc][2] = *(uint32_t*)&l; }
                h = __floats2bfloat162_rn(w12, w13); f = __bfloat1622float2(h);
                wh[nc][3] = *(uint32_t*)&h;
                { __nv_bfloat162 l = __floats2bfloat162_rn(w12 - f.x, w13 - f.y); wl[nc][3] = *(uint32_t*)&l; }
            }
        }

        // ---- GEMM-B: accK += w @ xk, accV += w @ xv (contraction n=128) ----
        {
            const uint32_t xrow = (uint32_t)(((lane >> 3) & 1) * 8 + (lane & 7));
            const uint32_t hcb = (((uint32_t)lane >> 4) & 1) * 16;
#pragma unroll
            for (int nc = 0; nc < 8; nc++) {
                const uint32_t row = xrow + nc * 16;
#pragma unroll
                for (int dc = 0; dc < 4; dc++) {
                    const uint32_t col = ((uint32_t)dc * 32 + hcb) ^ sx;
                    uint32_t bkh[4], bkl[4], bvh[4], bvl[4];
                    ldsm4t(bkh, sb + M_X(b, 0) + row * 128 + col);
                    ldsm4t(bkl, sb + M_X(b, 1) + row * 128 + col);
                    ldsm4t(bvh, sb + M_X(b, 2) + row * 128 + col);
                    ldsm4t(bvl, sb + M_X(b, 3) + row * 128 + col);
#pragma unroll
                    for (int g = 0; g < 2; g++) {
                        const int jd = dc * 2 + g;
                        mma_bf16(accK[jd], wh[nc], &bkh[g * 2]);
                        mma_bf16(accV[jd], wh[nc], &bvh[g * 2]);
                        mma_bf16(accK[jd], wh[nc], &bkl[g * 2]);
                        mma_bf16(accV[jd], wh[nc], &bvl[g * 2]);
                        mma_bf16(accK[jd], wl[nc], &bkh[g * 2]);
                        mma_bf16(accV[jd], wl[nc], &bvh[g * 2]);
                    }
                }
            }
        }
        __syncthreads();   // x(b) consumed before next prefetch overwrites it
    }

    // ---- S reduction within quad (each warp owns its 16 k-rows exclusively) ----
    sloc0 += __shfl_xor_sync(~0u, sloc0, 1);
    sloc0 += __shfl_xor_sync(~0u, sloc0, 2);
    sloc1 += __shfl_xor_sync(~0u, sloc1, 1);
    sloc1 += __shfl_xor_sync(~0u, sloc1, 2);
    const float rs0 = 1.0f / sloc0;
    const float rs1 = 1.0f / sloc1;

    // ---- finalize: gK = accK*rs - K, gV = accV*rs - V ----
    const int krow0 = k0 + wid * 16 + r;
#pragma unroll
    for (int jd = 0; jd < 8; jd++) {
        const int d = jd * 8 + 2 * q;
        size_t gi0 = ((size_t)bh * KP + krow0) * DD + d;
        size_t gi1 = ((size_t)bh * KP + krow0 + 8) * DD + d;
        float2 kv0 = *(const float2*)(K + gi0);
        float2 kv1 = *(const float2*)(K + gi1);
        float2 vv0 = *(const float2*)(V + gi0);
        float2 vv1 = *(const float2*)(V + gi1);
        float2 o;
        o.x = accK[jd][0] * rs0 - kv0.x; o.y = accK[jd][1] * rs0 - kv0.y;
        *(float2*)(out + gi0) = o;
        o.x = accK[jd][2] * rs1 - kv1.x; o.y = accK[jd][3] * rs1 - kv1.y;
        *(float2*)(out + gi1) = o;
        o.x = accV[jd][0] * rs0 - vv0.x; o.y = accV[jd][1] * rs0 - vv0.y;
        *(float2*)(out + (size_t)BH * KP * DD + gi0) = o;
        o.x = accV[jd][2] * rs1 - vv1.x; o.y = accV[jd][3] * rs1 - vv1.y;
        *(float2*)(out + (size_t)BH * KP * DD + gi1) = o;
    }
}

// ---------------------------------------------------------------- launch
extern "C" void kernel_launch(void* const* d_in, const int* in_sizes, int n_in,
                              void* d_out, int out_size) {
    (void)in_sizes; (void)n_in; (void)out_size;
    const float* K  = (const float*)d_in[0];
    const float* V  = (const float*)d_in[1];
    const float* xk = (const float*)d_in[2];
    const float* xv = (const float*)d_in[3];
    float* out = (float*)d_out;

    cudaFuncSetAttribute(hm_z,    cudaFuncAttributeMaxDynamicSharedMemorySize, Z_SMEM);
    cudaFuncSetAttribute(hm_main, cudaFuncAttributeMaxDynamicSharedMemorySize, M_SMEM);

    hm_split<<<dim3(BH * NN * DD / 4 / 256, 3), 256>>>(
        (const float4*)K, (const float4*)xk, (const float4*)xv);
    hm_z<<<dim3(NN / 128, BH), 256, Z_SMEM>>>();
    hm_main<<<dim3(KP / 128, BH), 256, M_SMEM>>>(K, V, out);
}

// round 10
// speedup vs baseline: 1.2598x; 1.1697x over previous
#include <cuda_runtime.h>
#include <cuda_bf16.h>
#include <stdint.h>

#define BH 64
#define KP 512
#define NN 4096
#define DD 64
#define XT 16384            // 128 x 64 bf16 tile, swizzled, 128B rows

// ---- hm_main smem layout (bytes): 3 x-arrays (xkhi, xklo, xvhi) x 2 buffers ----
#define M_X(b,c)  ((b) * 49152 + (c) * XT)
#define M_RZ  98304         // 2 x 512B raw z tiles
#define M_SMEM 99328

// ---- hm_z smem layout (unchanged, proven) ----
#define Z_XHI 0
#define Z_XLO XT
#define Z_K(b,c) (32768 + (b) * 32768 + (c) * XT)
#define Z_ZP 98304
#define Z_SMEM 99328

__device__ float g_z[BH * NN];
__device__ __align__(16) __nv_bfloat16 g_K_hi[BH * KP * DD];
__device__ __align__(16) __nv_bfloat16 g_K_lo[BH * KP * DD];
__device__ __align__(16) __nv_bfloat16 g_xk_hi[BH * NN * DD];
__device__ __align__(16) __nv_bfloat16 g_xk_lo[BH * NN * DD];
__device__ __align__(16) __nv_bfloat16 g_xv_hi[BH * NN * DD];

// ---------------------------------------------------------------- helpers
__device__ __forceinline__ uint32_t s2u(const void* p) {
    return (uint32_t)__cvta_generic_to_shared(p);
}
__device__ __forceinline__ void mma_bf16(float* c, const uint32_t* a, const uint32_t* b) {
    asm volatile(
        "mma.sync.aligned.m16n8k16.row.col.f32.bf16.bf16.f32 "
        "{%0,%1,%2,%3}, {%4,%5,%6,%7}, {%8,%9}, {%0,%1,%2,%3};"
        : "+f"(c[0]), "+f"(c[1]), "+f"(c[2]), "+f"(c[3])
        : "r"(a[0]), "r"(a[1]), "r"(a[2]), "r"(a[3]), "r"(b[0]), "r"(b[1]));
}
__device__ __forceinline__ void ldsm4(uint32_t* r, uint32_t addr) {
    asm volatile("ldmatrix.sync.aligned.m8n8.x4.shared.b16 {%0,%1,%2,%3}, [%4];"
        : "=r"(r[0]), "=r"(r[1]), "=r"(r[2]), "=r"(r[3]) : "r"(addr));
}
__device__ __forceinline__ void ldsm4t(uint32_t* r, uint32_t addr) {
    asm volatile("ldmatrix.sync.aligned.m8n8.x4.trans.shared.b16 {%0,%1,%2,%3}, [%4];"
        : "=r"(r[0]), "=r"(r[1]), "=r"(r[2]), "=r"(r[3]) : "r"(addr));
}
__device__ __forceinline__ void cpa(uint32_t dst, const void* src) {
    asm volatile("cp.async.cg.shared.global [%0], [%1], 16;" :: "r"(dst), "l"(src));
}
#define CPA_COMMIT() asm volatile("cp.async.commit_group;" ::: "memory")
__device__ __forceinline__ void cpa_wait1() { asm volatile("cp.async.wait_group 1;" ::: "memory"); }

// 128x64 bf16 tile (16KB) global -> swizzled smem (128B rows). 256 thr.
__device__ __forceinline__ void cpa_tile(uint32_t sbase, const __nv_bfloat16* g, int tid) {
#pragma unroll
    for (int j = 0; j < 4; j++) {
        int ch = tid + j * 256;
        int row = ch >> 3, c = ch & 7;
        uint32_t off = (uint32_t)row * 128 + (((uint32_t)c * 16) ^ (((uint32_t)row & 7) << 4));
        cpa(sbase + off, (const char*)g + (size_t)ch * 16);
    }
}

// GEMM-A (z pass layout): C[4 mb][4 j][4] += (Khi+Klo)[64k x 64d] @ (xhi+xlo)[32n x 64d]^T
__device__ __forceinline__ void gemmA(float C[4][4][4],
        uint32_t uKhi, uint32_t uKlo, uint32_t uXhi, uint32_t uXlo,
        int kw, int nw, int lane) {
    const uint32_t sx = ((uint32_t)lane & 7) << 4;
    const uint32_t ar = (uint32_t)(kw * 64 + (lane & 15));
    const uint32_t br = (uint32_t)(nw * 32 + ((lane >> 4) & 1) * 8 + (lane & 7));
#pragma unroll
    for (int kc = 0; kc < 4; kc++) {
        const uint32_t acol = ((((uint32_t)lane >> 4) & 1) * 16 + kc * 32) ^ sx;
        const uint32_t bcol = ((((uint32_t)lane >> 3) & 1) * 16 + kc * 32) ^ sx;
        uint32_t ah[4][4], al[4][4], bh2[2][4], bl2[2][4];
#pragma unroll
        for (int mb = 0; mb < 4; mb++) {
            ldsm4(ah[mb], uKhi + (ar + mb * 16) * 128 + acol);
            ldsm4(al[mb], uKlo + (ar + mb * 16) * 128 + acol);
        }
#pragma unroll
        for (int g = 0; g < 2; g++) {
            ldsm4(bh2[g], uXhi + (br + g * 16) * 128 + bcol);
            ldsm4(bl2[g], uXlo + (br + g * 16) * 128 + bcol);
        }
#pragma unroll
        for (int mb = 0; mb < 4; mb++)
#pragma unroll
            for (int g = 0; g < 2; g++)
#pragma unroll
                for (int nbb = 0; nbb < 2; nbb++)
                    mma_bf16(C[mb][g * 2 + nbb], ah[mb], &bh2[g][nbb * 2]);
#pragma unroll
        for (int mb = 0; mb < 4; mb++)
#pragma unroll
            for (int g = 0; g < 2; g++)
#pragma unroll
                for (int nbb = 0; nbb < 2; nbb++)
                    mma_bf16(C[mb][g * 2 + nbb], ah[mb], &bl2[g][nbb * 2]);
#pragma unroll
        for (int mb = 0; mb < 4; mb++)
#pragma unroll
            for (int g = 0; g < 2; g++)
#pragma unroll
                for (int nbb = 0; nbb < 2; nbb++)
                    mma_bf16(C[mb][g * 2 + nbb], al[mb], &bh2[g][nbb * 2]);
    }
}

// ---------------------------------------------------------------- split
// which: 0=K (hi+lo), 1=xk (hi+lo), 2=xv (hi only)
__global__ __launch_bounds__(256) void hm_split(const float4* __restrict__ Ksrc,
        const float4* __restrict__ xksrc, const float4* __restrict__ xvsrc) {
    int which = blockIdx.y;
    int n4 = (which == 0) ? (BH * KP * DD / 4) : (BH * NN * DD / 4);
    int i = blockIdx.x * 256 + threadIdx.x;
    if (i >= n4) return;
    const float4* src = (which == 0) ? Ksrc : (which == 1) ? xksrc : xvsrc;
    float4 v = src[i];
    __nv_bfloat162 h0 = __floats2bfloat162_rn(v.x, v.y);
    __nv_bfloat162 h1 = __floats2bfloat162_rn(v.z, v.w);
    uint2 hw;
    hw.x = *(uint32_t*)&h0; hw.y = *(uint32_t*)&h1;
    if (which == 2) { ((uint2*)g_xv_hi)[i] = hw; return; }
    float2 f0 = __bfloat1622float2(h0), f1 = __bfloat1622float2(h1);
    __nv_bfloat162 l0 = __floats2bfloat162_rn(v.x - f0.x, v.y - f0.y);
    __nv_bfloat162 l1 = __floats2bfloat162_rn(v.z - f1.x, v.w - f1.y);
    uint2 lw;
    lw.x = *(uint32_t*)&l0; lw.y = *(uint32_t*)&l1;
    __nv_bfloat16* hi = (which == 0) ? g_K_hi : g_xk_hi;
    __nv_bfloat16* lo = (which == 0) ? g_K_lo : g_xk_lo;
    ((uint2*)hi)[i] = hw;
    ((uint2*)lo)[i] = lw;
}

// ---------------------------------------------------------------- pass 1: z (unchanged)
__global__ __launch_bounds__(256) void hm_z() {
    extern __shared__ char sm[];
    const int tid = threadIdx.x, lane = tid & 31, wid = tid >> 5;
    const int kw = wid >> 2, nw = wid & 3;
    const int n0 = blockIdx.x * 128, bh = blockIdx.y;
    uint32_t sb = s2u(sm);

    cpa_tile(sb + Z_XHI, g_xk_hi + ((size_t)bh * NN + n0) * DD, tid);
    cpa_tile(sb + Z_XLO, g_xk_lo + ((size_t)bh * NN + n0) * DD, tid);
    cpa_tile(sb + Z_K(0, 0), g_K_hi + (size_t)bh * KP * DD, tid);
    cpa_tile(sb + Z_K(0, 1), g_K_lo + (size_t)bh * KP * DD, tid);
    CPA_COMMIT();

    float zl[8];
#pragma unroll
    for (int i = 0; i < 8; i++) zl[i] = 0.f;

    for (int kt = 0; kt < 4; kt++) {
        if (kt + 1 < 4) {
            cpa_tile(sb + Z_K((kt + 1) & 1, 0), g_K_hi + ((size_t)bh * KP + (kt + 1) * 128) * DD, tid);
            cpa_tile(sb + Z_K((kt + 1) & 1, 1), g_K_lo + ((size_t)bh * KP + (kt + 1) * 128) * DD, tid);
        }
        CPA_COMMIT();
        cpa_wait1();
        __syncthreads();

        float C[4][4][4];
#pragma unroll
        for (int a = 0; a < 4; a++)
#pragma unroll
            for (int b = 0; b < 4; b++)
#pragma unroll
                for (int c = 0; c < 4; c++) C[a][b][c] = 0.f;
        gemmA(C, sb + Z_K(kt & 1, 0), sb + Z_K(kt & 1, 1), sb + Z_XHI, sb + Z_XLO, kw, nw, lane);
#pragma unroll
        for (int mb = 0; mb < 4; mb++)
#pragma unroll
            for (int j = 0; j < 4; j++) {
                zl[2 * j]     += __expf(C[mb][j][0]) + __expf(C[mb][j][2]);
                zl[2 * j + 1] += __expf(C[mb][j][1]) + __expf(C[mb][j][3]);
            }
        __syncthreads();
    }
#pragma unroll
    for (int i = 0; i < 8; i++) {
        zl[i] += __shfl_xor_sync(~0u, zl[i], 4);
        zl[i] += __shfl_xor_sync(~0u, zl[i], 8);
        zl[i] += __shfl_xor_sync(~0u, zl[i], 16);
    }
    float* zp = (float*)(sm + Z_ZP);
    if (lane < 4) {
#pragma unroll
        for (int j = 0; j < 4; j++)
            *(float2*)&zp[kw * 128 + nw * 32 + j * 8 + lane * 2] =
                make_float2(zl[2 * j], zl[2 * j + 1]);
    }
    __syncthreads();
    if (tid < 128)
        g_z[(size_t)bh * NN + n0 + tid] = zp[tid] + zp[128 + tid];
}

// ---------------------------------------------------------------- pass 2
// CTA = (bh, 128-k tile). Warp owns 16 k-rows; w stays in registers (C-frag ==
// A-frag identity). GEMM-B uses x_hi only (w 2-term), saving 1/3 of MMAs and
// half of GEMM-B LDSM traffic.
__global__ __launch_bounds__(256) void hm_main(const float* __restrict__ K,
        const float* __restrict__ V, float* __restrict__ out) {
    extern __shared__ char sm[];
    const int tid = threadIdx.x, lane = tid & 31, wid = tid >> 5;
    const int k0 = blockIdx.x * 128, bh = blockIdx.y;
    uint32_t sb = s2u(sm);
    const uint32_t sx = ((uint32_t)lane & 7) << 4;
    const int q = lane & 3, r = lane >> 2;

    // K A-fragments held in registers for the whole kernel (4 kc x hi/lo x 4).
    uint32_t kfh[4][4], kfl[4][4];
    cpa_tile(sb + M_X(0, 0), g_K_hi + ((size_t)bh * KP + k0) * DD, tid);
    cpa_tile(sb + M_X(0, 1), g_K_lo + ((size_t)bh * KP + k0) * DD, tid);
    CPA_COMMIT();
    asm volatile("cp.async.wait_group 0;" ::: "memory");
    __syncthreads();
    {
        const uint32_t ar = (uint32_t)(wid * 16 + (lane & 15));
#pragma unroll
        for (int kc = 0; kc < 4; kc++) {
            const uint32_t acol = ((((uint32_t)lane >> 4) & 1) * 16 + kc * 32) ^ sx;
            ldsm4(kfh[kc], sb + M_X(0, 0) + ar * 128 + acol);
            ldsm4(kfl[kc], sb + M_X(0, 1) + ar * 128 + acol);
        }
    }
    __syncthreads();

    // x(0) + z(0)
    cpa_tile(sb + M_X(0, 0), g_xk_hi + (size_t)bh * NN * DD, tid);
    cpa_tile(sb + M_X(0, 1), g_xk_lo + (size_t)bh * NN * DD, tid);
    cpa_tile(sb + M_X(0, 2), g_xv_hi + (size_t)bh * NN * DD, tid);
    if (tid < 32) cpa(sb + M_RZ + tid * 16, g_z + (size_t)bh * NN + tid * 4);
    CPA_COMMIT();

    float accK[8][4], accV[8][4];
#pragma unroll
    for (int a = 0; a < 8; a++)
#pragma unroll
        for (int c = 0; c < 4; c++) { accK[a][c] = 0.f; accV[a][c] = 0.f; }
    float sloc0 = 0.f, sloc1 = 0.f;

    for (int it = 0; it < NN / 128; it++) {
        const int b = it & 1;
        if (it + 1 < NN / 128) {
            const size_t n1 = (size_t)bh * NN + (size_t)(it + 1) * 128;
            cpa_tile(sb + M_X(b ^ 1, 0), g_xk_hi + n1 * DD, tid);
            cpa_tile(sb + M_X(b ^ 1, 1), g_xk_lo + n1 * DD, tid);
            cpa_tile(sb + M_X(b ^ 1, 2), g_xv_hi + n1 * DD, tid);
            if (tid < 32) cpa(sb + M_RZ + (b ^ 1) * 512 + tid * 16, g_z + n1 + tid * 4);
        }
        CPA_COMMIT();
        cpa_wait1();
        __syncthreads();

        // ---- GEMM-A: C[16 j][4] = K[16k x 64d] @ x[128n x 64d]^T, 3-term ----
        float C[16][4];
#pragma unroll
        for (int j = 0; j < 16; j++)
#pragma unroll
            for (int c = 0; c < 4; c++) C[j][c] = 0.f;
        {
            const uint32_t uXhi = sb + M_X(b, 0), uXlo = sb + M_X(b, 1);
            const uint32_t br = (uint32_t)(((lane >> 4) & 1) * 8 + (lane & 7));
#pragma unroll
            for (int kc = 0; kc < 4; kc++) {
                const uint32_t bcol = ((((uint32_t)lane >> 3) & 1) * 16 + kc * 32) ^ sx;
                uint32_t bh2[8][4], bl2[8][4];
#pragma unroll
                for (int jj = 0; jj < 8; jj++) {
                    ldsm4(bh2[jj], uXhi + (br + jj * 16) * 128 + bcol);
                    ldsm4(bl2[jj], uXlo + (br + jj * 16) * 128 + bcol);
                }
#pragma unroll
                for (int jj = 0; jj < 8; jj++) {
                    mma_bf16(C[2 * jj],     kfh[kc], &bh2[jj][0]);
                    mma_bf16(C[2 * jj + 1], kfh[kc], &bh2[jj][2]);
                }
#pragma unroll
                for (int jj = 0; jj < 8; jj++) {
                    mma_bf16(C[2 * jj],     kfh[kc], &bl2[jj][0]);
                    mma_bf16(C[2 * jj + 1], kfh[kc], &bl2[jj][2]);
                }
#pragma unroll
                for (int jj = 0; jj < 8; jj++) {
                    mma_bf16(C[2 * jj],     kfl[kc], &bh2[jj][0]);
                    mma_bf16(C[2 * jj + 1], kfl[kc], &bh2[jj][2]);
                }
            }
        }

        // ---- epilogue in registers: w = exp(C)/z -> bf16 hi/lo A-fragments ----
        uint32_t wh[8][4], wl[8][4];
        {
            const float* zb = (const float*)(sm + M_RZ + b * 512);
#pragma unroll
            for (int nc = 0; nc < 8; nc++) {
                float2 z0 = *(const float2*)&zb[nc * 16 + 2 * q];
                float2 z1 = *(const float2*)&zb[nc * 16 + 8 + 2 * q];
                float r0 = __fdividef(1.f, z0.x), r1 = __fdividef(1.f, z0.y);
                float r2 = __fdividef(1.f, z1.x), r3 = __fdividef(1.f, z1.y);
                float w00 = __expf(C[2 * nc][0]) * r0,  w01 = __expf(C[2 * nc][1]) * r1;
                float w02 = __expf(C[2 * nc][2]) * r0,  w03 = __expf(C[2 * nc][3]) * r1;
                float w10 = __expf(C[2 * nc + 1][0]) * r2, w11 = __expf(C[2 * nc + 1][1]) * r3;
                float w12 = __expf(C[2 * nc + 1][2]) * r2, w13 = __expf(C[2 * nc + 1][3]) * r3;
                sloc0 += (w00 + w01) + (w10 + w11);
                sloc1 += (w02 + w03) + (w12 + w13);
                __nv_bfloat162 h;
                float2 f;
                h = __floats2bfloat162_rn(w00, w01); f = __bfloat1622float2(h);
                wh[nc][0] = *(uint32_t*)&h;
                { __nv_bfloat162 l = __floats2bfloat162_rn(w00 - f.x, w01 - f.y); wl[nc][0] = *(uint32_t*)&l; }
                h = __floats2bfloat162_rn(w02, w03); f = __bfloat1622float2(h);
                wh[nc][1] = *(uint32_t*)&h;
                { __nv_bfloat162 l = __floats2bfloat162_rn(w02 - f.x, w03 - f.y); wl[nc][1] = *(uint32_t*)&l; }
                h = __floats2bfloat162_rn(w10, w11); f = __bfloat1622float2(h);
                wh[nc][2] = *(uint32_t*)&h;
                { __nv_bfloat162 l = __floats2bfloat162_rn(w10 - f.x, w11 - f.y); wl[nc][2] = *(uint32_t*)&l; }
                h = __floats2bfloat162_rn(w12, w13); f = __bfloat1622float2(h);
                wh[nc][3] = *(uint32_t*)&h;
                { __nv_bfloat162 l = __floats2bfloat162_rn(w12 - f.x, w13 - f.y); wl[nc][3] = *(uint32_t*)&l; }
            }
        }

        // ---- GEMM-B: accK += w @ xk_hi, accV += w @ xv_hi (w 2-term) ----
        {
            const uint32_t xrow = (uint32_t)(((lane >> 3) & 1) * 8 + (lane & 7));
            const uint32_t hcb = (((uint32_t)lane >> 4) & 1) * 16;
#pragma unroll
            for (int nc = 0; nc < 8; nc++) {
                const uint32_t row = xrow + nc * 16;
#pragma unroll
                for (int dc = 0; dc < 4; dc++) {
                    const uint32_t col = ((uint32_t)dc * 32 + hcb) ^ sx;
                    uint32_t bkh[4], bvh[4];
                    ldsm4t(bkh, sb + M_X(b, 0) + row * 128 + col);
                    ldsm4t(bvh, sb + M_X(b, 2) + row * 128 + col);
#pragma unroll
                    for (int g = 0; g < 2; g++) {
                        const int jd = dc * 2 + g;
                        mma_bf16(accK[jd], wh[nc], &bkh[g * 2]);
                        mma_bf16(accV[jd], wh[nc], &bvh[g * 2]);
                        mma_bf16(accK[jd], wl[nc], &bkh[g * 2]);
                        mma_bf16(accV[jd], wl[nc], &bvh[g * 2]);
                    }
                }
            }
        }
        __syncthreads();   // x(b) consumed before next prefetch overwrites it
    }

    // ---- S reduction within quad (warp owns its 16 k-rows exclusively) ----
    sloc0 += __shfl_xor_sync(~0u, sloc0, 1);
    sloc0 += __shfl_xor_sync(~0u, sloc0, 2);
    sloc1 += __shfl_xor_sync(~0u, sloc1, 1);
    sloc1 += __shfl_xor_sync(~0u, sloc1, 2);
    const float rs0 = 1.0f / sloc0;
    const float rs1 = 1.0f / sloc1;

    // ---- finalize: gK = accK*rs - K, gV = accV*rs - V ----
    const int krow0 = k0 + wid * 16 + r;
#pragma unroll
    for (int jd = 0; jd < 8; jd++) {
        const int d = jd * 8 + 2 * q;
        size_t gi0 = ((size_t)bh * KP + krow0) * DD + d;
        size_t gi1 = ((size_t)bh * KP + krow0 + 8) * DD + d;
        float2 kv0 = *(const float2*)(K + gi0);
        float2 kv1 = *(const float2*)(K + gi1);
        float2 vv0 = *(const float2*)(V + gi0);
        float2 vv1 = *(const float2*)(V + gi1);
        float2 o;
        o.x = accK[jd][0] * rs0 - kv0.x; o.y = accK[jd][1] * rs0 - kv0.y;
        *(float2*)(out + gi0) = o;
        o.x = accK[jd][2] * rs1 - kv1.x; o.y = accK[jd][3] * rs1 - kv1.y;
        *(float2*)(out + gi1) = o;
        o.x = accV[jd][0] * rs0 - vv0.x; o.y = accV[jd][1] * rs0 - vv0.y;
        *(float2*)(out + (size_t)BH * KP * DD + gi0) = o;
        o.x = accV[jd][2] * rs1 - vv1.x; o.y = accV[jd][3] * rs1 - vv1.y;
        *(float2*)(out + (size_t)BH * KP * DD + gi1) = o;
    }
}

// ---------------------------------------------------------------- launch
extern "C" void kernel_launch(void* const* d_in, const int* in_sizes, int n_in,
                              void* d_out, int out_size) {
    (void)in_sizes; (void)n_in; (void)out_size;
    const float* K  = (const float*)d_in[0];
    const float* V  = (const float*)d_in[1];
    const float* xk = (const float*)d_in[2];
    const float* xv = (const float*)d_in[3];
    float* out = (float*)d_out;

    cudaFuncSetAttribute(hm_z,    cudaFuncAttributeMaxDynamicSharedMemorySize, Z_SMEM);
    cudaFuncSetAttribute(hm_main, cudaFuncAttributeMaxDynamicSharedMemorySize, M_SMEM);

    hm_split<<<dim3(BH * NN * DD / 4 / 256, 3), 256>>>(
        (const float4*)K, (const float4*)xk, (const float4*)xv);
    hm_z<<<dim3(NN / 128, BH), 256, Z_SMEM>>>();
    hm_main<<<dim3(KP / 128, BH), 256, M_SMEM>>>(K, V, out);
}

// round 11
// speedup vs baseline: 1.5156x; 1.2031x over previous
#include <cuda_runtime.h>
#include <cuda_fp16.h>
#include <stdint.h>

#define BH 64
#define KP 512
#define NN 4096
#define DD 64
#define XT 16384            // 128 x 64 fp16 tile, swizzled, 128B rows

// ---- hm_main smem layout (bytes): 3 x-arrays (xkhi, xklo, xvhi) x 2 buffers ----
#define M_X(b,c)  ((b) * 49152 + (c) * XT)
#define M_RZ  98304         // 2 x 512B raw z tiles
#define M_SMEM 99328

// ---- hm_z smem layout ----
#define Z_XHI 0
#define Z_XLO XT
#define Z_K(b,c) (32768 + (b) * 32768 + (c) * XT)
#define Z_ZP 98304
#define Z_SMEM 99328

__device__ float g_z[BH * NN];
__device__ __align__(16) __half g_K_hi[BH * KP * DD];
__device__ __align__(16) __half g_K_lo[BH * KP * DD];
__device__ __align__(16) __half g_xk_hi[BH * NN * DD];
__device__ __align__(16) __half g_xk_lo[BH * NN * DD];
__device__ __align__(16) __half g_xv_hi[BH * NN * DD];

// ---------------------------------------------------------------- helpers
__device__ __forceinline__ uint32_t s2u(const void* p) {
    return (uint32_t)__cvta_generic_to_shared(p);
}
__device__ __forceinline__ void mma_f16(float* c, const uint32_t* a, const uint32_t* b) {
    asm volatile(
        "mma.sync.aligned.m16n8k16.row.col.f32.f16.f16.f32 "
        "{%0,%1,%2,%3}, {%4,%5,%6,%7}, {%8,%9}, {%0,%1,%2,%3};"
        : "+f"(c[0]), "+f"(c[1]), "+f"(c[2]), "+f"(c[3])
        : "r"(a[0]), "r"(a[1]), "r"(a[2]), "r"(a[3]), "r"(b[0]), "r"(b[1]));
}
__device__ __forceinline__ void ldsm4(uint32_t* r, uint32_t addr) {
    asm volatile("ldmatrix.sync.aligned.m8n8.x4.shared.b16 {%0,%1,%2,%3}, [%4];"
        : "=r"(r[0]), "=r"(r[1]), "=r"(r[2]), "=r"(r[3]) : "r"(addr));
}
__device__ __forceinline__ void ldsm4t(uint32_t* r, uint32_t addr) {
    asm volatile("ldmatrix.sync.aligned.m8n8.x4.trans.shared.b16 {%0,%1,%2,%3}, [%4];"
        : "=r"(r[0]), "=r"(r[1]), "=r"(r[2]), "=r"(r[3]) : "r"(addr));
}
__device__ __forceinline__ void cpa(uint32_t dst, const void* src) {
    asm volatile("cp.async.cg.shared.global [%0], [%1], 16;" :: "r"(dst), "l"(src));
}
#define CPA_COMMIT() asm volatile("cp.async.commit_group;" ::: "memory")
__device__ __forceinline__ void cpa_wait1() { asm volatile("cp.async.wait_group 1;" ::: "memory"); }

// 128x64 fp16 tile (16KB) global -> swizzled smem (128B rows). 256 thr.
__device__ __forceinline__ void cpa_tile(uint32_t sbase, const __half* g, int tid) {
#pragma unroll
    for (int j = 0; j < 4; j++) {
        int ch = tid + j * 256;
        int row = ch >> 3, c = ch & 7;
        uint32_t off = (uint32_t)row * 128 + (((uint32_t)c * 16) ^ (((uint32_t)row & 7) << 4));
        cpa(sbase + off, (const char*)g + (size_t)ch * 16);
    }
}

// GEMM-A (z pass layout): C[4 mb][4 j][4] += (Khi+Klo)[64k x 64d] @ (xhi+xlo)[32n x 64d]^T
__device__ __forceinline__ void gemmA(float C[4][4][4],
        uint32_t uKhi, uint32_t uKlo, uint32_t uXhi, uint32_t uXlo,
        int kw, int nw, int lane) {
    const uint32_t sx = ((uint32_t)lane & 7) << 4;
    const uint32_t ar = (uint32_t)(kw * 64 + (lane & 15));
    const uint32_t br = (uint32_t)(nw * 32 + ((lane >> 4) & 1) * 8 + (lane & 7));
#pragma unroll
    for (int kc = 0; kc < 4; kc++) {
        const uint32_t acol = ((((uint32_t)lane >> 4) & 1) * 16 + kc * 32) ^ sx;
        const uint32_t bcol = ((((uint32_t)lane >> 3) & 1) * 16 + kc * 32) ^ sx;
        uint32_t ah[4][4], al[4][4], bh2[2][4], bl2[2][4];
#pragma unroll
        for (int mb = 0; mb < 4; mb++) {
            ldsm4(ah[mb], uKhi + (ar + mb * 16) * 128 + acol);
            ldsm4(al[mb], uKlo + (ar + mb * 16) * 128 + acol);
        }
#pragma unroll
        for (int g = 0; g < 2; g++) {
            ldsm4(bh2[g], uXhi + (br + g * 16) * 128 + bcol);
            ldsm4(bl2[g], uXlo + (br + g * 16) * 128 + bcol);
        }
#pragma unroll
        for (int mb = 0; mb < 4; mb++)
#pragma unroll
            for (int g = 0; g < 2; g++)
#pragma unroll
                for (int nbb = 0; nbb < 2; nbb++)
                    mma_f16(C[mb][g * 2 + nbb], ah[mb], &bh2[g][nbb * 2]);
#pragma unroll
        for (int mb = 0; mb < 4; mb++)
#pragma unroll
            for (int g = 0; g < 2; g++)
#pragma unroll
                for (int nbb = 0; nbb < 2; nbb++)
                    mma_f16(C[mb][g * 2 + nbb], ah[mb], &bl2[g][nbb * 2]);
#pragma unroll
        for (int mb = 0; mb < 4; mb++)
#pragma unroll
            for (int g = 0; g < 2; g++)
#pragma unroll
                for (int nbb = 0; nbb < 2; nbb++)
                    mma_f16(C[mb][g * 2 + nbb], al[mb], &bh2[g][nbb * 2]);
    }
}

// ---------------------------------------------------------------- split
// which: 0=K (hi+lo), 1=xk (hi+lo), 2=xv (hi only)  -- fp16 split
__global__ __launch_bounds__(256) void hm_split(const float4* __restrict__ Ksrc,
        const float4* __restrict__ xksrc, const float4* __restrict__ xvsrc) {
    int which = blockIdx.y;
    int n4 = (which == 0) ? (BH * KP * DD / 4) : (BH * NN * DD / 4);
    int i = blockIdx.x * 256 + threadIdx.x;
    if (i >= n4) return;
    const float4* src = (which == 0) ? Ksrc : (which == 1) ? xksrc : xvsrc;
    float4 v = src[i];
    __half2 h0 = __floats2half2_rn(v.x, v.y);
    __half2 h1 = __floats2half2_rn(v.z, v.w);
    uint2 hw;
    hw.x = *(uint32_t*)&h0; hw.y = *(uint32_t*)&h1;
    if (which == 2) { ((uint2*)g_xv_hi)[i] = hw; return; }
    float2 f0 = __half22float2(h0), f1 = __half22float2(h1);
    __half2 l0 = __floats2half2_rn(v.x - f0.x, v.y - f0.y);
    __half2 l1 = __floats2half2_rn(v.z - f1.x, v.w - f1.y);
    uint2 lw;
    lw.x = *(uint32_t*)&l0; lw.y = *(uint32_t*)&l1;
    __half* hi = (which == 0) ? g_K_hi : g_xk_hi;
    __half* lo = (which == 0) ? g_K_lo : g_xk_lo;
    ((uint2*)hi)[i] = hw;
    ((uint2*)lo)[i] = lw;
}

// ---------------------------------------------------------------- pass 1: z
__global__ __launch_bounds__(256) void hm_z() {
    extern __shared__ char sm[];
    const int tid = threadIdx.x, lane = tid & 31, wid = tid >> 5;
    const int kw = wid >> 2, nw = wid & 3;
    const int n0 = blockIdx.x * 128, bh = blockIdx.y;
    uint32_t sb = s2u(sm);

    cpa_tile(sb + Z_XHI, g_xk_hi + ((size_t)bh * NN + n0) * DD, tid);
    cpa_tile(sb + Z_XLO, g_xk_lo + ((size_t)bh * NN + n0) * DD, tid);
    cpa_tile(sb + Z_K(0, 0), g_K_hi + (size_t)bh * KP * DD, tid);
    cpa_tile(sb + Z_K(0, 1), g_K_lo + (size_t)bh * KP * DD, tid);
    CPA_COMMIT();

    float zl[8];
#pragma unroll
    for (int i = 0; i < 8; i++) zl[i] = 0.f;

    for (int kt = 0; kt < 4; kt++) {
        if (kt + 1 < 4) {
            cpa_tile(sb + Z_K((kt + 1) & 1, 0), g_K_hi + ((size_t)bh * KP + (kt + 1) * 128) * DD, tid);
            cpa_tile(sb + Z_K((kt + 1) & 1, 1), g_K_lo + ((size_t)bh * KP + (kt + 1) * 128) * DD, tid);
        }
        CPA_COMMIT();
        cpa_wait1();
        __syncthreads();

        float C[4][4][4];
#pragma unroll
        for (int a = 0; a < 4; a++)
#pragma unroll
            for (int b = 0; b < 4; b++)
#pragma unroll
                for (int c = 0; c < 4; c++) C[a][b][c] = 0.f;
        gemmA(C, sb + Z_K(kt & 1, 0), sb + Z_K(kt & 1, 1), sb + Z_XHI, sb + Z_XLO, kw, nw, lane);
#pragma unroll
        for (int mb = 0; mb < 4; mb++)
#pragma unroll
            for (int j = 0; j < 4; j++) {
                zl[2 * j]     += __expf(C[mb][j][0]) + __expf(C[mb][j][2]);
                zl[2 * j + 1] += __expf(C[mb][j][1]) + __expf(C[mb][j][3]);
            }
        __syncthreads();
    }
#pragma unroll
    for (int i = 0; i < 8; i++) {
        zl[i] += __shfl_xor_sync(~0u, zl[i], 4);
        zl[i] += __shfl_xor_sync(~0u, zl[i], 8);
        zl[i] += __shfl_xor_sync(~0u, zl[i], 16);
    }
    float* zp = (float*)(sm + Z_ZP);
    if (lane < 4) {
#pragma unroll
        for (int j = 0; j < 4; j++)
            *(float2*)&zp[kw * 128 + nw * 32 + j * 8 + lane * 2] =
                make_float2(zl[2 * j], zl[2 * j + 1]);
    }
    __syncthreads();
    if (tid < 128)
        g_z[(size_t)bh * NN + n0 + tid] = zp[tid] + zp[128 + tid];
}

// ---------------------------------------------------------------- pass 2
// CTA = (bh, 128-k tile). Warp owns 16 k-rows; w stays in registers (C-frag ==
// A-frag identity). fp16 precision: GEMM-B is single-term (w_hi @ x_hi).
__global__ __launch_bounds__(256) void hm_main(const float* __restrict__ K,
        const float* __restrict__ V, float* __restrict__ out) {
    extern __shared__ char sm[];
    const int tid = threadIdx.x, lane = tid & 31, wid = tid >> 5;
    const int k0 = blockIdx.x * 128, bh = blockIdx.y;
    uint32_t sb = s2u(sm);
    const uint32_t sx = ((uint32_t)lane & 7) << 4;
    const int q = lane & 3, r = lane >> 2;

    // K A-fragments in registers (4 kc x hi/lo x 4)
    uint32_t kfh[4][4], kfl[4][4];
    cpa_tile(sb + M_X(0, 0), g_K_hi + ((size_t)bh * KP + k0) * DD, tid);
    cpa_tile(sb + M_X(0, 1), g_K_lo + ((size_t)bh * KP + k0) * DD, tid);
    CPA_COMMIT();
    asm volatile("cp.async.wait_group 0;" ::: "memory");
    __syncthreads();
    {
        const uint32_t ar = (uint32_t)(wid * 16 + (lane & 15));
#pragma unroll
        for (int kc = 0; kc < 4; kc++) {
            const uint32_t acol = ((((uint32_t)lane >> 4) & 1) * 16 + kc * 32) ^ sx;
            ldsm4(kfh[kc], sb + M_X(0, 0) + ar * 128 + acol);
            ldsm4(kfl[kc], sb + M_X(0, 1) + ar * 128 + acol);
        }
    }
    __syncthreads();

    // x(0) + z(0)
    cpa_tile(sb + M_X(0, 0), g_xk_hi + (size_t)bh * NN * DD, tid);
    cpa_tile(sb + M_X(0, 1), g_xk_lo + (size_t)bh * NN * DD, tid);
    cpa_tile(sb + M_X(0, 2), g_xv_hi + (size_t)bh * NN * DD, tid);
    if (tid < 32) cpa(sb + M_RZ + tid * 16, g_z + (size_t)bh * NN + tid * 4);
    CPA_COMMIT();

    float accK[8][4], accV[8][4];
#pragma unroll
    for (int a = 0; a < 8; a++)
#pragma unroll
        for (int c = 0; c < 4; c++) { accK[a][c] = 0.f; accV[a][c] = 0.f; }
    float sloc0 = 0.f, sloc1 = 0.f;

    for (int it = 0; it < NN / 128; it++) {
        const int b = it & 1;
        if (it + 1 < NN / 128) {
            const size_t n1 = (size_t)bh * NN + (size_t)(it + 1) * 128;
            cpa_tile(sb + M_X(b ^ 1, 0), g_xk_hi + n1 * DD, tid);
            cpa_tile(sb + M_X(b ^ 1, 1), g_xk_lo + n1 * DD, tid);
            cpa_tile(sb + M_X(b ^ 1, 2), g_xv_hi + n1 * DD, tid);
            if (tid < 32) cpa(sb + M_RZ + (b ^ 1) * 512 + tid * 16, g_z + n1 + tid * 4);
        }
        CPA_COMMIT();
        cpa_wait1();
        __syncthreads();

        // ---- GEMM-A: C[16 j][4] = K[16k x 64d] @ x[128n x 64d]^T, 3-term ----
        float C[16][4];
#pragma unroll
        for (int j = 0; j < 16; j++)
#pragma unroll
            for (int c = 0; c < 4; c++) C[j][c] = 0.f;
        {
            const uint32_t uXhi = sb + M_X(b, 0), uXlo = sb + M_X(b, 1);
            const uint32_t br = (uint32_t)(((lane >> 4) & 1) * 8 + (lane & 7));
#pragma unroll
            for (int kc = 0; kc < 4; kc++) {
                const uint32_t bcol = ((((uint32_t)lane >> 3) & 1) * 16 + kc * 32) ^ sx;
                uint32_t bh2[8][4], bl2[8][4];
#pragma unroll
                for (int jj = 0; jj < 8; jj++) {
                    ldsm4(bh2[jj], uXhi + (br + jj * 16) * 128 + bcol);
                    ldsm4(bl2[jj], uXlo + (br + jj * 16) * 128 + bcol);
                }
#pragma unroll
                for (int jj = 0; jj < 8; jj++) {
                    mma_f16(C[2 * jj],     kfh[kc], &bh2[jj][0]);
                    mma_f16(C[2 * jj + 1], kfh[kc], &bh2[jj][2]);
                }
#pragma unroll
                for (int jj = 0; jj < 8; jj++) {
                    mma_f16(C[2 * jj],     kfh[kc], &bl2[jj][0]);
                    mma_f16(C[2 * jj + 1], kfh[kc], &bl2[jj][2]);
                }
#pragma unroll
                for (int jj = 0; jj < 8; jj++) {
                    mma_f16(C[2 * jj],     kfl[kc], &bh2[jj][0]);
                    mma_f16(C[2 * jj + 1], kfl[kc], &bh2[jj][2]);
                }
            }
        }

        // ---- epilogue in registers: w = exp(C)/z -> fp16 A-fragments ----
        uint32_t wh[8][4];
        {
            const float* zb = (const float*)(sm + M_RZ + b * 512);
#pragma unroll
            for (int nc = 0; nc < 8; nc++) {
                float2 z0 = *(const float2*)&zb[nc * 16 + 2 * q];
                float2 z1 = *(const float2*)&zb[nc * 16 + 8 + 2 * q];
                float r0 = __fdividef(1.f, z0.x), r1 = __fdividef(1.f, z0.y);
                float r2 = __fdividef(1.f, z1.x), r3 = __fdividef(1.f, z1.y);
                float w00 = __expf(C[2 * nc][0]) * r0,  w01 = __expf(C[2 * nc][1]) * r1;
                float w02 = __expf(C[2 * nc][2]) * r0,  w03 = __expf(C[2 * nc][3]) * r1;
                float w10 = __expf(C[2 * nc + 1][0]) * r2, w11 = __expf(C[2 * nc + 1][1]) * r3;
                float w12 = __expf(C[2 * nc + 1][2]) * r2, w13 = __expf(C[2 * nc + 1][3]) * r3;
                sloc0 += (w00 + w01) + (w10 + w11);
                sloc1 += (w02 + w03) + (w12 + w13);
                __half2 h;
                h = __floats2half2_rn(w00, w01); wh[nc][0] = *(uint32_t*)&h;
                h = __floats2half2_rn(w02, w03); wh[nc][1] = *(uint32_t*)&h;
                h = __floats2half2_rn(w10, w11); wh[nc][2] = *(uint32_t*)&h;
                h = __floats2half2_rn(w12, w13); wh[nc][3] = *(uint32_t*)&h;
            }
        }

        // ---- GEMM-B: accK += w @ xk_hi, accV += w @ xv_hi (single term) ----
        {
            const uint32_t xrow = (uint32_t)(((lane >> 3) & 1) * 8 + (lane & 7));
            const uint32_t hcb = (((uint32_t)lane >> 4) & 1) * 16;
#pragma unroll
            for (int nc = 0; nc < 8; nc++) {
                const uint32_t row = xrow + nc * 16;
#pragma unroll
                for (int dc = 0; dc < 4; dc++) {
                    const uint32_t col = ((uint32_t)dc * 32 + hcb) ^ sx;
                    uint32_t bkh[4], bvh[4];
                    ldsm4t(bkh, sb + M_X(b, 0) + row * 128 + col);
                    ldsm4t(bvh, sb + M_X(b, 2) + row * 128 + col);
#pragma unroll
                    for (int g = 0; g < 2; g++) {
                        const int jd = dc * 2 + g;
                        mma_f16(accK[jd], wh[nc], &bkh[g * 2]);
                        mma_f16(accV[jd], wh[nc], &bvh[g * 2]);
                    }
                }
            }
        }
        __syncthreads();   // x(b) consumed before next prefetch overwrites it
    }

    // ---- S reduction within quad (warp owns its 16 k-rows exclusively) ----
    sloc0 += __shfl_xor_sync(~0u, sloc0, 1);
    sloc0 += __shfl_xor_sync(~0u, sloc0, 2);
    sloc1 += __shfl_xor_sync(~0u, sloc1, 1);
    sloc1 += __shfl_xor_sync(~0u, sloc1, 2);
    const float rs0 = 1.0f / sloc0;
    const float rs1 = 1.0f / sloc1;

    // ---- finalize: gK = accK*rs - K, gV = accV*rs - V ----
    const int krow0 = k0 + wid * 16 + r;
#pragma unroll
    for (int jd = 0; jd < 8; jd++) {
        const int d = jd * 8 + 2 * q;
        size_t gi0 = ((size_t)bh * KP + krow0) * DD + d;
        size_t gi1 = ((size_t)bh * KP + krow0 + 8) * DD + d;
        float2 kv0 = *(const float2*)(K + gi0);
        float2 kv1 = *(const float2*)(K + gi1);
        float2 vv0 = *(const float2*)(V + gi0);
        float2 vv1 = *(const float2*)(V + gi1);
        float2 o;
        o.x = accK[jd][0] * rs0 - kv0.x; o.y = accK[jd][1] * rs0 - kv0.y;
        *(float2*)(out + gi0) = o;
        o.x = accK[jd][2] * rs1 - kv1.x; o.y = accK[jd][3] * rs1 - kv1.y;
        *(float2*)(out + gi1) = o;
        o.x = accV[jd][0] * rs0 - vv0.x; o.y = accV[jd][1] * rs0 - vv0.y;
        *(float2*)(out + (size_t)BH * KP * DD + gi0) = o;
        o.x = accV[jd][2] * rs1 - vv1.x; o.y = accV[jd][3] * rs1 - vv1.y;
        *(float2*)(out + (size_t)BH * KP * DD + gi1) = o;
    }
}

// ---------------------------------------------------------------- launch
extern "C" void kernel_launch(void* const* d_in, const int* in_sizes, int n_in,
                              void* d_out, int out_size) {
    (void)in_sizes; (void)n_in; (void)out_size;
    const float* K  = (const float*)d_in[0];
    const float* V  = (const float*)d_in[1];
    const float* xk = (const float*)d_in[2];
    const float* xv = (const float*)d_in[3];
    float* out = (float*)d_out;

    cudaFuncSetAttribute(hm_z,    cudaFuncAttributeMaxDynamicSharedMemorySize, Z_SMEM);
    cudaFuncSetAttribute(hm_main, cudaFuncAttributeMaxDynamicSharedMemorySize, M_SMEM);

    hm_split<<<dim3(BH * NN * DD / 4 / 256, 3), 256>>>(
        (const float4*)K, (const float4*)xk, (const float4*)xv);
    hm_z<<<dim3(NN / 128, BH), 256, Z_SMEM>>>();
    hm_main<<<dim3(KP / 128, BH), 256, M_SMEM>>>(K, V, out);
}